// round 15
// baseline (speedup 1.0000x reference)
#include <cuda_runtime.h>
#include <cuda_fp16.h>
#include <cstdint>

#define B_ 32
#define C_ 256
#define HW_ 4096
#define K_ 32
#define THREADS 256
#define TILE_T 64
#define TILES 8
#define NBLOCKS 256          // b*8 + chunk, 512 tokens per block

// ---- smem byte offsets ----
#define XROW  0              // f16 [64 tok][264 half] stride 132 u32 (33792 B)
#define XCMO  33792          // f16 [256 ch][72 half]  stride 36 u32  (36864 B)
#define CWC   70656          // f16 [32 code][264 half]               (16896 B)
#define WCO   87552          // f16 [32 code][72 half] stride 36 u32  (4608 B)
#define LGO   92160          // f32 logits [64 tok][36]               (9216 B)
#define XSQP  101376         // f32 [8 seg][64 tok]                   (2048 B)
#define CSQO  103424
#define SCLO  103552
#define WSMO  103680
#define SMEM_BYTES 103808    // -> 2 CTAs/SM

__device__ float g_part[NBLOCKS * K_ * C_];
__device__ float g_wsp[NBLOCKS * K_];

__device__ __forceinline__ uint32_t pk(float lo, float hi) {
    __half2 h = __floats2half2_rn(lo, hi);
    return *(uint32_t*)&h;
}
__device__ __forceinline__ void mma_f16(float c[4],
        uint32_t a0, uint32_t a1, uint32_t a2, uint32_t a3, uint32_t b0, uint32_t b1) {
    asm volatile("mma.sync.aligned.m16n8k16.row.col.f32.f16.f16.f32 "
        "{%0,%1,%2,%3}, {%4,%5,%6,%7}, {%8,%9}, {%0,%1,%2,%3};"
        : "+f"(c[0]), "+f"(c[1]), "+f"(c[2]), "+f"(c[3])
        : "r"(a0), "r"(a1), "r"(a2), "r"(a3), "r"(b0), "r"(b1));
}

__global__ void __launch_bounds__(THREADS, 2)
enc_main(const float* __restrict__ x, const float* __restrict__ cw,
         const float* __restrict__ scale, float* __restrict__ out)
{
    extern __shared__ char base[];
    uint32_t* XR  = (uint32_t*)(base + XROW);
    uint32_t* XC2 = (uint32_t*)(base + XCMO);
    uint32_t* CW2 = (uint32_t*)(base + CWC);
    uint32_t* W2  = (uint32_t*)(base + WCO);
    __half*   WCh = (__half*)(base + WCO);
    float* LG  = (float*)(base + LGO);
    float* XQ  = (float*)(base + XSQP);
    float* CSQ = (float*)(base + CSQO);
    float* SCL = (float*)(base + SCLO);
    float* WSM = (float*)(base + WSMO);

    const int t = threadIdx.x, w = t >> 5, lane = t & 31;
    const int q = lane & 3, g = lane >> 2;
    const int b = blockIdx.x >> 3, chunk = blockIdx.x & 7;
    const float* xb = x + (size_t)b * (C_ * HW_);
    const int base_n0 = chunk * (TILE_T * TILES);

    // ---- prologue ----
    if (t < K_) { SCL[t] = scale[t]; WSM[t] = 0.f; }
    {
        int code = t >> 3, p = t & 7;
        const float* cr = cw + code * C_ + p * 32;
        float s = 0.f;
        #pragma unroll
        for (int i = 0; i < 32; i++) s += cr[i] * cr[i];
        s += __shfl_xor_sync(~0u, s, 1); s += __shfl_xor_sync(~0u, s, 2); s += __shfl_xor_sync(~0u, s, 4);
        if (p == 0) CSQ[code] = s;
    }
    #pragma unroll
    for (int e = t; e < 4096; e += THREADS) {   // CW f16, pairs along ch
        int code = e >> 7, cp = e & 127;
        CW2[code * 132 + cp] = pk(cw[code * C_ + 2 * cp], cw[code * C_ + 2 * cp + 1]);
    }

    float acc[2][4][4];
    #pragma unroll
    for (int i = 0; i < 2; i++)
        #pragma unroll
        for (int j = 0; j < 4; j++)
            #pragma unroll
            for (int r = 0; r < 4; r++) acc[i][j][r] = 0.f;
    float wsum_acc[8];
    #pragma unroll
    for (int j = 0; j < 8; j++) wsum_acc[j] = 0.f;

    __syncthreads();

    for (int tile = 0; tile < TILES; tile++) {
        const int n0 = base_n0 + tile * TILE_T;

        // ---- load+repack: thread owns token-pair (2tp,2tp+1) x 32 ch ----
        // 32 lanes (same cs) x float2 = 256B coalesced per channel row
        {
            const int tp = t & 31, cs = t >> 5;
            const float* src = xb + n0 + 2 * tp;
            float xq0 = 0.f, xq1 = 0.f;
            #pragma unroll
            for (int i = 0; i < 32; i += 2) {
                int c = cs * 32 + i;
                float2 p0 = *(const float2*)(src + (size_t)c * HW_);
                float2 p1 = *(const float2*)(src + (size_t)(c + 1) * HW_);
                xq0 += p0.x * p0.x + p1.x * p1.x;
                xq1 += p0.y * p0.y + p1.y * p1.y;
                XC2[c * 36 + tp]       = pk(p0.x, p0.y);   // k=tok pairs
                XC2[(c + 1) * 36 + tp] = pk(p1.x, p1.y);
                XR[(2 * tp) * 132 + cs * 16 + (i >> 1)]     = pk(p0.x, p1.x);  // k=ch pairs
                XR[(2 * tp + 1) * 132 + cs * 16 + (i >> 1)] = pk(p0.y, p1.y);
            }
            XQ[cs * 64 + 2 * tp] = xq0;
            XQ[cs * 64 + 2 * tp + 1] = xq1;
        }
        __syncthreads();

        // ---- G1: logits[64 tok x 32 code] = X * CW^T, K=256 (16 chunks) ----
        {
            const int mt = w >> 1, nh = w & 1;
            const int tokr = mt * 16 + g;
            float cfr[2][4] = {{0,0,0,0},{0,0,0,0}};
            #pragma unroll
            for (int kc = 0; kc < 16; kc++) {
                int kb = kc * 8 + q;
                uint32_t a0 = XR[tokr * 132 + kb];
                uint32_t a1 = XR[(tokr + 8) * 132 + kb];
                uint32_t a2 = XR[tokr * 132 + kb + 4];
                uint32_t a3 = XR[(tokr + 8) * 132 + kb + 4];
                #pragma unroll
                for (int ntl = 0; ntl < 2; ntl++) {
                    int crow = (nh * 2 + ntl) * 8 + g;
                    uint32_t b0 = CW2[crow * 132 + kb];
                    uint32_t b1 = CW2[crow * 132 + kb + 4];
                    mma_f16(cfr[ntl], a0, a1, a2, a3, b0, b1);
                }
            }
            #pragma unroll
            for (int ntl = 0; ntl < 2; ntl++) {
                int col = (nh * 2 + ntl) * 8 + 2 * q;
                *(float2*)(LG + tokr * 36 + col)       = make_float2(cfr[ntl][0], cfr[ntl][1]);
                *(float2*)(LG + (tokr + 8) * 36 + col) = make_float2(cfr[ntl][2], cfr[ntl][3]);
            }
        }
        __syncthreads();

        // ---- softmax per token (ALL 256 threads; 64 tok x 4 lanes) ----
        {
            const int row = t >> 2, qq = t & 3;
            float4 va = *(const float4*)(LG + row * 36 + qq * 8);
            float4 vb = *(const float4*)(LG + row * 36 + qq * 8 + 4);
            float xc8[8] = {va.x, va.y, va.z, va.w, vb.x, vb.y, vb.z, vb.w};
            float xsq = 0.f;
            #pragma unroll
            for (int s = 0; s < 8; s++) xsq += XQ[s * 64 + row];
            float lg[8], mx = -1e30f;
            #pragma unroll
            for (int j = 0; j < 8; j++) {
                int k = qq * 8 + j;
                lg[j] = SCL[k] * (xsq - 2.f * xc8[j] + CSQ[k]);
                mx = fmaxf(mx, lg[j]);
            }
            mx = fmaxf(mx, __shfl_xor_sync(~0u, mx, 1));
            mx = fmaxf(mx, __shfl_xor_sync(~0u, mx, 2));
            float sum = 0.f;
            #pragma unroll
            for (int j = 0; j < 8; j++) { lg[j] = __expf(lg[j] - mx); sum += lg[j]; }
            sum += __shfl_xor_sync(~0u, sum, 1);
            sum += __shfl_xor_sync(~0u, sum, 2);
            float inv = __fdividef(1.f, sum);
            #pragma unroll
            for (int j = 0; j < 8; j++) {
                float v = lg[j] * inv;
                wsum_acc[j] += v;
                WCh[(qq * 8 + j) * 72 + row] = __float2half_rn(v);
            }
        }
        __syncthreads();

        // ---- G2: D[256 ch x 32 code] += X^T * W, K=64 tok (4 chunks) ----
        {
            const int chb = w * 32;
            #pragma unroll
            for (int kc = 0; kc < 4; kc++) {
                int kb = kc * 8 + q;
                uint32_t bw[4][2];
                #pragma unroll
                for (int nt = 0; nt < 4; nt++) {
                    bw[nt][0] = W2[(nt * 8 + g) * 36 + kb];
                    bw[nt][1] = W2[(nt * 8 + g) * 36 + kb + 4];
                }
                #pragma unroll
                for (int mtc = 0; mtc < 2; mtc++) {
                    int chr = chb + mtc * 16 + g;
                    uint32_t a0 = XC2[chr * 36 + kb];
                    uint32_t a1 = XC2[(chr + 8) * 36 + kb];
                    uint32_t a2 = XC2[chr * 36 + kb + 4];
                    uint32_t a3 = XC2[(chr + 8) * 36 + kb + 4];
                    #pragma unroll
                    for (int nt = 0; nt < 4; nt++)
                        mma_f16(acc[mtc][nt], a0, a1, a2, a3, bw[nt][0], bw[nt][1]);
                }
            }
        }
        __syncthreads();   // G2 done before next repack overwrites buffers
    }

    // ---- epilogue: write partials ----
    #pragma unroll
    for (int j = 0; j < 8; j++) {
        float v = wsum_acc[j];
        v += __shfl_xor_sync(~0u, v, 4); v += __shfl_xor_sync(~0u, v, 8); v += __shfl_xor_sync(~0u, v, 16);
        if (g == 0) atomicAdd(&WSM[q * 8 + j], v);
    }
    __syncthreads();
    if (t < K_) g_wsp[blockIdx.x * K_ + t] = WSM[t];

    float* pb = g_part + (size_t)blockIdx.x * (K_ * C_);
    {
        const int chb = w * 32;
        #pragma unroll
        for (int mtc = 0; mtc < 2; mtc++)
            #pragma unroll
            for (int nt = 0; nt < 4; nt++) {
                int ch = chb + mtc * 16 + g;
                int code = nt * 8 + 2 * q;
                pb[code * C_ + ch]             = acc[mtc][nt][0];
                pb[(code + 1) * C_ + ch]       = acc[mtc][nt][1];
                pb[code * C_ + ch + 8]         = acc[mtc][nt][2];
                pb[(code + 1) * C_ + ch + 8]   = acc[mtc][nt][3];
            }
    }
}

__global__ void enc_finalize(float* __restrict__ out, const float* __restrict__ cw) {
    int i = blockIdx.x * 256 + threadIdx.x;          // covers 262144 = B*K*C
    int b = i >> 13, k = (i >> 8) & (K_ - 1), c = i & (C_ - 1);
    const float* pb = g_part + (size_t)(b * 8) * (K_ * C_) + k * C_ + c;
    const float* wp = g_wsp + b * 8 * K_ + k;
    float s = 0.f, ws = 0.f;
    #pragma unroll
    for (int ck = 0; ck < 8; ck++) {
        s  += pb[(size_t)ck * (K_ * C_)];
        ws += wp[ck * K_];
    }
    out[i] = s - ws * cw[k * C_ + c];
}

extern "C" void kernel_launch(void* const* d_in, const int* in_sizes, int n_in,
                              void* d_out, int out_size) {
    const float* x = (const float*)d_in[0];
    const float* cwp = (const float*)d_in[1];
    const float* scale = (const float*)d_in[2];
    float* out = (float*)d_out;
    cudaFuncSetAttribute(enc_main, cudaFuncAttributeMaxDynamicSharedMemorySize, SMEM_BYTES);
    enc_main<<<NBLOCKS, THREADS, SMEM_BYTES>>>(x, cwp, scale, out);
    enc_finalize<<<(B_ * K_ * C_) / 256, 256>>>(out, cwp);
}

// round 16
// speedup vs baseline: 1.1094x; 1.1094x over previous
#include <cuda_runtime.h>
#include <cuda_fp16.h>
#include <cstdint>

#define B_ 32
#define C_ 256
#define HW_ 4096
#define K_ 32
#define THREADS 256
#define TILE_T 32
#define CHUNKS 13            // blocks per batch; 128 tiles split 9-or-10 per block
#define NBLOCKS (B_ * CHUNKS)   // 416 blocks -> one full wave at 3 CTAs/SM
#define TILES_PER_BATCH 128

// ---- smem byte offsets (identical to R14 winner) ----
#define XROW  0              // f16 [32 tok][264 half]  stride 132 words (16896 B)
#define XCMO  16896          // f16 [256 ch][40 half]   stride 20 words  (20480 B)
#define CWC   37376          // f16 [32 code][264 half]                  (16896 B)
#define WCO   54272          // f16 [32 code][40 half]                   (2560 B)
#define LGO   56832          // f32 logits [32 tok][36]                  (4608 B)
#define XSQP  61440          // f32 [16 seg][32 tok]                     (2048 B)
#define CSQO  63488          // 32 f32
#define SCLO  63616          // 32 f32
#define WSMO  63744          // 32 f32
#define SMEM_BYTES 63872     // -> 3 CTAs/SM

__device__ float g_part[NBLOCKS * K_ * C_];
__device__ float g_wsp[NBLOCKS * K_];

__device__ __forceinline__ uint32_t pk(float lo, float hi) {
    __half2 h = __floats2half2_rn(lo, hi);
    return *(uint32_t*)&h;
}
__device__ __forceinline__ void mma_f16(float c[4],
        uint32_t a0, uint32_t a1, uint32_t a2, uint32_t a3, uint32_t b0, uint32_t b1) {
    asm volatile("mma.sync.aligned.m16n8k16.row.col.f32.f16.f16.f32 "
        "{%0,%1,%2,%3}, {%4,%5,%6,%7}, {%8,%9}, {%0,%1,%2,%3};"
        : "+f"(c[0]), "+f"(c[1]), "+f"(c[2]), "+f"(c[3])
        : "r"(a0), "r"(a1), "r"(a2), "r"(a3), "r"(b0), "r"(b1));
}

__global__ void __launch_bounds__(THREADS, 3)
enc_main(const float* __restrict__ x, const float* __restrict__ cw,
         const float* __restrict__ scale, float* __restrict__ out)
{
    extern __shared__ char base[];
    uint32_t* XR  = (uint32_t*)(base + XROW);
    uint32_t* XC2 = (uint32_t*)(base + XCMO);
    uint32_t* CW2 = (uint32_t*)(base + CWC);
    uint32_t* W2  = (uint32_t*)(base + WCO);
    __half*   WCh = (__half*)(base + WCO);
    float* LG  = (float*)(base + LGO);
    float* XQ  = (float*)(base + XSQP);
    float* CSQ = (float*)(base + CSQO);
    float* SCL = (float*)(base + SCLO);
    float* WSM = (float*)(base + WSMO);

    const int t = threadIdx.x, w = t >> 5, lane = t & 31;
    const int q = lane & 3, g = lane >> 2;
    const int b = blockIdx.x / CHUNKS, chunk = blockIdx.x % CHUNKS;
    const float* xb = x + (size_t)b * (C_ * HW_);
    // this block's tile range within the batch (sums exactly to 128)
    const int tile0 = (chunk * TILES_PER_BATCH) / CHUNKS;
    const int tile1 = ((chunk + 1) * TILES_PER_BATCH) / CHUNKS;

    // ---- prologue ----
    if (t < K_) { SCL[t] = scale[t]; WSM[t] = 0.f; }
    {
        int code = t >> 3, p = t & 7;
        const float* cr = cw + code * C_ + p * 32;
        float s = 0.f;
        #pragma unroll
        for (int i = 0; i < 32; i++) s += cr[i] * cr[i];
        s += __shfl_xor_sync(~0u, s, 1); s += __shfl_xor_sync(~0u, s, 2); s += __shfl_xor_sync(~0u, s, 4);
        if (p == 0) CSQ[code] = s;
    }
    #pragma unroll
    for (int e = t; e < 4096; e += THREADS) {   // CW f16, pairs along ch
        int code = e >> 7, cp = e & 127;
        CW2[code * 132 + cp] = pk(cw[code * C_ + 2 * cp], cw[code * C_ + 2 * cp + 1]);
    }

    float acc[2][4][4];
    #pragma unroll
    for (int i = 0; i < 2; i++)
        #pragma unroll
        for (int j = 0; j < 4; j++)
            #pragma unroll
            for (int r = 0; r < 4; r++) acc[i][j][r] = 0.f;
    float wsum_acc[8];
    #pragma unroll
    for (int j = 0; j < 8; j++) wsum_acc[j] = 0.f;

    __syncthreads();

    for (int tile = tile0; tile < tile1; tile++) {
        const int n0 = tile * TILE_T;

        // ---- load+repack: thread owns token-pair (2tp,2tp+1) x 16 ch -----
        {
            const int tp = t & 15, cs = t >> 4;
            const float* src = xb + n0 + 2 * tp;
            float xq0 = 0.f, xq1 = 0.f;
            float v[2][16];
            #pragma unroll
            for (int i = 0; i < 16; i++) {
                int c = cs * 16 + i;
                float2 pr = *(const float2*)(src + (size_t)c * HW_);
                v[0][i] = pr.x; v[1][i] = pr.y;
                xq0 += pr.x * pr.x; xq1 += pr.y * pr.y;
                XC2[c * 20 + tp] = pk(pr.x, pr.y);     // k=tok pairs
            }
            #pragma unroll
            for (int i = 0; i < 16; i += 2) {          // k=ch pairs
                XR[(2 * tp) * 132 + cs * 8 + (i >> 1)]     = pk(v[0][i], v[0][i + 1]);
                XR[(2 * tp + 1) * 132 + cs * 8 + (i >> 1)] = pk(v[1][i], v[1][i + 1]);
            }
            XQ[cs * 32 + 2 * tp] = xq0;
            XQ[cs * 32 + 2 * tp + 1] = xq1;
        }
        __syncthreads();

        // ---- G1: logits[32 tok x 32 code] = X * CW^T, K=256 (16 chunks) ----
        {
            const int mt = w >> 2, nh = w & 3;
            const int tokr = mt * 16 + g, crow = nh * 8 + g;
            float cfr[4] = {0, 0, 0, 0};
            #pragma unroll
            for (int kc = 0; kc < 16; kc++) {
                int kb = kc * 8 + q;
                uint32_t a0 = XR[tokr * 132 + kb];
                uint32_t a1 = XR[(tokr + 8) * 132 + kb];
                uint32_t a2 = XR[tokr * 132 + kb + 4];
                uint32_t a3 = XR[(tokr + 8) * 132 + kb + 4];
                uint32_t b0 = CW2[crow * 132 + kb];
                uint32_t b1 = CW2[crow * 132 + kb + 4];
                mma_f16(cfr, a0, a1, a2, a3, b0, b1);
            }
            int col = nh * 8 + 2 * q;
            *(float2*)(LG + tokr * 36 + col) = make_float2(cfr[0], cfr[1]);
            *(float2*)(LG + (tokr + 8) * 36 + col) = make_float2(cfr[2], cfr[3]);
        }
        __syncthreads();

        // ---- softmax per token (threads 0-127), W -> f16 [code][tok] ----
        if (t < 128) {
            const int row = t >> 2, qq = t & 3;
            float4 va = *(const float4*)(LG + row * 36 + qq * 8);
            float4 vb = *(const float4*)(LG + row * 36 + qq * 8 + 4);
            float xc8[8] = {va.x, va.y, va.z, va.w, vb.x, vb.y, vb.z, vb.w};
            float xsq = 0.f;
            #pragma unroll
            for (int s = 0; s < 16; s++) xsq += XQ[s * 32 + row];
            float lg[8], mx = -1e30f;
            #pragma unroll
            for (int j = 0; j < 8; j++) {
                int k = qq * 8 + j;
                lg[j] = SCL[k] * (xsq - 2.f * xc8[j] + CSQ[k]);
                mx = fmaxf(mx, lg[j]);
            }
            mx = fmaxf(mx, __shfl_xor_sync(~0u, mx, 1));
            mx = fmaxf(mx, __shfl_xor_sync(~0u, mx, 2));
            float sum = 0.f;
            #pragma unroll
            for (int j = 0; j < 8; j++) { lg[j] = __expf(lg[j] - mx); sum += lg[j]; }
            sum += __shfl_xor_sync(~0u, sum, 1);
            sum += __shfl_xor_sync(~0u, sum, 2);
            float inv = __fdividef(1.f, sum);
            #pragma unroll
            for (int j = 0; j < 8; j++) {
                float v = lg[j] * inv;
                wsum_acc[j] += v;
                WCh[(qq * 8 + j) * 40 + row] = __float2half_rn(v);
            }
        }
        __syncthreads();

        // ---- G2: D[256 ch x 32 code] += X^T * W, K=32 tok (2 chunks) ----
        {
            const int chb = w * 32;
            #pragma unroll
            for (int kc = 0; kc < 2; kc++) {
                int kb = kc * 8 + q;
                uint32_t bw[4][2];
                #pragma unroll
                for (int nt = 0; nt < 4; nt++) {
                    bw[nt][0] = W2[(nt * 8 + g) * 20 + kb];
                    bw[nt][1] = W2[(nt * 8 + g) * 20 + kb + 4];
                }
                #pragma unroll
                for (int mtc = 0; mtc < 2; mtc++) {
                    int chr = chb + mtc * 16 + g;
                    uint32_t a0 = XC2[chr * 20 + kb];
                    uint32_t a1 = XC2[(chr + 8) * 20 + kb];
                    uint32_t a2 = XC2[chr * 20 + kb + 4];
                    uint32_t a3 = XC2[(chr + 8) * 20 + kb + 4];
                    #pragma unroll
                    for (int nt = 0; nt < 4; nt++)
                        mma_f16(acc[mtc][nt], a0, a1, a2, a3, bw[nt][0], bw[nt][1]);
                }
            }
        }
        __syncthreads();   // G2 done before next repack overwrites XC2/W2
    }

    // ---- epilogue: write partials ----
    if (t < 128) {
        #pragma unroll
        for (int j = 0; j < 8; j++) {
            float v = wsum_acc[j];
            v += __shfl_xor_sync(~0u, v, 4); v += __shfl_xor_sync(~0u, v, 8); v += __shfl_xor_sync(~0u, v, 16);
            if ((lane >> 2) == 0) atomicAdd(&WSM[(lane & 3) * 8 + j], v);
        }
    }
    __syncthreads();
    if (t < K_) g_wsp[blockIdx.x * K_ + t] = WSM[t];

    float* pb = g_part + (size_t)blockIdx.x * (K_ * C_);
    {
        const int chb = w * 32;
        #pragma unroll
        for (int mtc = 0; mtc < 2; mtc++)
            #pragma unroll
            for (int nt = 0; nt < 4; nt++) {
                int ch = chb + mtc * 16 + g;
                int code = nt * 8 + 2 * q;
                pb[code * C_ + ch]             = acc[mtc][nt][0];
                pb[(code + 1) * C_ + ch]       = acc[mtc][nt][1];
                pb[code * C_ + ch + 8]         = acc[mtc][nt][2];
                pb[(code + 1) * C_ + ch + 8]   = acc[mtc][nt][3];
            }
    }
}

__global__ void enc_finalize(float* __restrict__ out, const float* __restrict__ cw) {
    int i = blockIdx.x * 256 + threadIdx.x;          // covers 262144 = B*K*C
    int b = i >> 13, k = (i >> 8) & (K_ - 1), c = i & (C_ - 1);
    const float* pb = g_part + (size_t)(b * CHUNKS) * (K_ * C_) + k * C_ + c;
    const float* wp = g_wsp + b * CHUNKS * K_ + k;
    float s = 0.f, ws = 0.f;
    #pragma unroll
    for (int ck = 0; ck < CHUNKS; ck++) {
        s  += pb[(size_t)ck * (K_ * C_)];
        ws += wp[ck * K_];
    }
    out[i] = s - ws * cw[k * C_ + c];
}

extern "C" void kernel_launch(void* const* d_in, const int* in_sizes, int n_in,
                              void* d_out, int out_size) {
    const float* x = (const float*)d_in[0];
    const float* cwp = (const float*)d_in[1];
    const float* scale = (const float*)d_in[2];
    float* out = (float*)d_out;
    cudaFuncSetAttribute(enc_main, cudaFuncAttributeMaxDynamicSharedMemorySize, SMEM_BYTES);
    enc_main<<<NBLOCKS, THREADS, SMEM_BYTES>>>(x, cwp, scale, out);
    enc_finalize<<<(B_ * K_ * C_) / 256, 256>>>(out, cwp);
}